// round 17
// baseline (speedup 1.0000x reference)
#include <cuda_runtime.h>
#include <cstdint>

// Problem constants
//  B=8, SQ=SK=1024, D_MODEL=1024, H=16, DK=DV=64
//  out   : (8,1024,1024)        = 8388608 floats   at d_out[0]
//  attn  : (8,16,1024,1024)     = 134217728 floats at d_out[8388608] (if present)

#define OUT_ELEMS 8388608

// ---------------- scratch (device globals: allocation-free) ----------------
__device__ float g_Qh[8388608];       // (B,H,S,64)
__device__ float g_Kh[8388608];
__device__ float g_Vh[8388608];
__device__ float g_ctx[8388608];      // (B,S,H*64)
__device__ float g_attn[134217728];   // fallback if attn not part of d_out

// ---------------- tf32 helpers (attn kernel) ----------------
__device__ __forceinline__ uint32_t f2tf(float x) {
    uint32_t u;
    asm("cvt.rna.tf32.f32 %0, %1;" : "=r"(u) : "f"(x));
    return u;
}
__device__ __forceinline__ void tfsplit(float x, uint32_t& h, uint32_t& l) {
    h = f2tf(x);
    l = f2tf(x - __uint_as_float(h));
}
__device__ __forceinline__ void mma8(float c[4], const uint32_t a[4], const uint32_t b[2]) {
    asm volatile(
        "mma.sync.aligned.m16n8k8.row.col.f32.tf32.tf32.f32 "
        "{%0,%1,%2,%3}, {%4,%5,%6,%7}, {%8,%9}, {%0,%1,%2,%3};"
        : "+f"(c[0]), "+f"(c[1]), "+f"(c[2]), "+f"(c[3])
        : "r"(a[0]), "r"(a[1]), "r"(a[2]), "r"(a[3]), "r"(b[0]), "r"(b[1]));
}

// ---------------- bf16 helpers (GEMM) ----------------
// split pair (x=k even, y=k+1): h = {hi=bf16(y), lo=bf16(x)}, l = same for residuals
__device__ __forceinline__ void bfsplit2(float x, float y, uint32_t& h, uint32_t& l) {
    asm("cvt.rn.bf16x2.f32 %0, %1, %2;" : "=r"(h) : "f"(y), "f"(x));
    float rx = x - __uint_as_float(h << 16);
    float ry = y - __uint_as_float(h & 0xffff0000u);
    asm("cvt.rn.bf16x2.f32 %0, %1, %2;" : "=r"(l) : "f"(ry), "f"(rx));
}
__device__ __forceinline__ void mma16(float c[4], const uint32_t a[4], const uint32_t b[2]) {
    asm volatile(
        "mma.sync.aligned.m16n8k16.row.col.f32.bf16.bf16.f32 "
        "{%0,%1,%2,%3}, {%4,%5,%6,%7}, {%8,%9}, {%0,%1,%2,%3};"
        : "+f"(c[0]), "+f"(c[1]), "+f"(c[2]), "+f"(c[3])
        : "r"(a[0]), "r"(a[1]), "r"(a[2]), "r"(a[3]), "r"(b[0]), "r"(b[1]));
}

// ---------------- GEMM: C(8192x1024) = A(8192x1024) @ W(1024x1024) + bias ----------------
// 3-term split-bf16 (AhWh + AlWh + AhWl; dropped AlWl ~2^-18 -> stage RMS ~4e-6).
// bf16 m16n8k16 runs at 2x tf32-flop rate -> 1.33x over 2-term tf32.
// Smem: AH/AL u32[128][16] (k-pairs, stride 16 words: stores lane%8 quads, reads 16r+q — both
// conflict-free); WH/WL u32[128 cols][17] pair-packed over k (stores 4*lane%32, reads 17c+q).
// permute=1: write head-major (B,H,S,64); permute=0: plain row-major.
__global__ void __launch_bounds__(256, 2) gemm_bf16(const float* __restrict__ A,
                                                    const float* __restrict__ W,
                                                    const float* __restrict__ bias,
                                                    float* __restrict__ out,
                                                    int permute) {
    extern __shared__ uint32_t smg[];
    uint32_t* AH = smg;                 // [128][16]  (16 k-pairs = BK 32)
    uint32_t* AL = AH + 2048;
    uint32_t* WH = AL + 2048;           // [128][17]  (16 k-pairs + pad)
    uint32_t* WL = WH + 2176;
    // total 8448 words = 33792 B

    const int tid  = threadIdx.x;
    const int lane = tid & 31;
    const int warp = tid >> 5;
    const int wm   = warp & 3;      // 4 warps along M (32 rows each)
    const int wn   = warp >> 2;     // 2 warps along N (64 cols each)
    const int bm0  = blockIdx.y << 7;
    const int bn0  = blockIdx.x << 7;
    const int ra   = lane >> 2;
    const int qc   = lane & 3;

    float c[2][8][4];
#pragma unroll
    for (int i = 0; i < 2; i++)
#pragma unroll
        for (int j = 0; j < 8; j++)
#pragma unroll
            for (int k = 0; k < 4; k++) c[i][j][k] = 0.f;

    for (int kt = 0; kt < 32; kt++) {
        // ---- A tile (128x32) -> AH/AL pair planes ----
#pragma unroll
        for (int i = 0; i < 2; i++) {
            int item = tid + (i << 8);
            int r = item >> 2, kg = item & 3;        // 8 floats per item
            const float* src = A + (size_t)(bm0 + r) * 1024 + (kt << 5) + kg * 8;
            float4 v0 = *reinterpret_cast<const float4*>(src);
            float4 v1 = *reinterpret_cast<const float4*>(src + 4);
            uint4 h, l;
            bfsplit2(v0.x, v0.y, h.x, l.x);
            bfsplit2(v0.z, v0.w, h.y, l.y);
            bfsplit2(v1.x, v1.y, h.z, l.z);
            bfsplit2(v1.z, v1.w, h.w, l.w);
            reinterpret_cast<uint4*>(AH)[r * 4 + kg] = h;
            reinterpret_cast<uint4*>(AL)[r * 4 + kg] = l;
        }
        // ---- W tile (32x128) -> WH/WL pair-packed [col][kp] ----
#pragma unroll
        for (int i = 0; i < 2; i++) {
            int item = tid + (i << 8);
            int kp = item >> 5, c4 = (item & 31) << 2;
            const float* s0 = W + (size_t)((kt << 5) + 2 * kp) * 1024 + bn0 + c4;
            float4 r0 = *reinterpret_cast<const float4*>(s0);
            float4 r1 = *reinterpret_cast<const float4*>(s0 + 1024);   // k row +1
            uint32_t h, l;
            bfsplit2(r0.x, r1.x, h, l); WH[(c4 + 0) * 17 + kp] = h; WL[(c4 + 0) * 17 + kp] = l;
            bfsplit2(r0.y, r1.y, h, l); WH[(c4 + 1) * 17 + kp] = h; WL[(c4 + 1) * 17 + kp] = l;
            bfsplit2(r0.z, r1.z, h, l); WH[(c4 + 2) * 17 + kp] = h; WL[(c4 + 2) * 17 + kp] = l;
            bfsplit2(r0.w, r1.w, h, l); WH[(c4 + 3) * 17 + kp] = h; WL[(c4 + 3) * 17 + kp] = l;
        }
        __syncthreads();

#pragma unroll
        for (int s = 0; s < 2; s++) {           // two k16 steps per kt
            int kb = s << 3;                    // pair-index base
            uint32_t ah[2][4], al[2][4];
#pragma unroll
            for (int mt = 0; mt < 2; mt++) {
                int row = wm * 32 + mt * 16 + ra;
                ah[mt][0] = AH[row * 16 + kb + qc];
                ah[mt][1] = AH[(row + 8) * 16 + kb + qc];
                ah[mt][2] = AH[row * 16 + kb + qc + 4];
                ah[mt][3] = AH[(row + 8) * 16 + kb + qc + 4];
                al[mt][0] = AL[row * 16 + kb + qc];
                al[mt][1] = AL[(row + 8) * 16 + kb + qc];
                al[mt][2] = AL[row * 16 + kb + qc + 4];
                al[mt][3] = AL[(row + 8) * 16 + kb + qc + 4];
            }
#pragma unroll
            for (int nt = 0; nt < 8; nt++) {
                int col = wn * 64 + nt * 8 + ra;
                uint32_t bh[2] = { WH[col * 17 + kb + qc], WH[col * 17 + kb + qc + 4] };
                uint32_t bl[2] = { WL[col * 17 + kb + qc], WL[col * 17 + kb + qc + 4] };
                mma16(c[0][nt], ah[0], bh);
                mma16(c[0][nt], al[0], bh);
                mma16(c[0][nt], ah[0], bl);
                mma16(c[1][nt], ah[1], bh);
                mma16(c[1][nt], al[1], bh);
                mma16(c[1][nt], ah[1], bl);
            }
        }
        __syncthreads();
    }

    // epilogue: bias + (optionally permuted) stores (identical layout to tf32 version)
#pragma unroll
    for (int mt = 0; mt < 2; mt++) {
        int m0 = bm0 + wm * 32 + mt * 16 + ra;
#pragma unroll
        for (int nt = 0; nt < 8; nt++) {
            int n0 = bn0 + wn * 64 + nt * 8 + (qc << 1);
            float b0 = bias[n0], b1 = bias[n0 + 1];
            float2 v01 = make_float2(c[mt][nt][0] + b0, c[mt][nt][1] + b1);
            float2 v23 = make_float2(c[mt][nt][2] + b0, c[mt][nt][3] + b1);
            if (permute) {
                int bb = m0 >> 10, s = m0 & 1023, h = n0 >> 6, j = n0 & 63;
                float* p = out + (((size_t)(bb * 16 + h)) << 16) + (s << 6) + j;
                *reinterpret_cast<float2*>(p) = v01;
                *reinterpret_cast<float2*>(p + 512) = v23;      // row s+8
            } else {
                float* p = out + (size_t)m0 * 1024 + n0;
                *reinterpret_cast<float2*>(p) = v01;
                *reinterpret_cast<float2*>(p + 8192) = v23;     // row m0+8
            }
        }
    }
}

// ---------------- fused attention (byte-identical to R14 passing kernel) ----------------
// Pass A (2-term QK: Q split hi/lo planes, K tf32-hi): 8 warps 4(M:32 rows)x2(N:64-key half).
//   Fixed-shift softmax p~ = exp(l*0.125 + mask*(-1e9) - 16).
// Pass B (2-term PV): warp = 16 rows, full 64 dims (race-free).
__global__ void __launch_bounds__(256, 2) attn_kernel(const float* __restrict__ mask,
                                                      float* __restrict__ attn) {
    extern __shared__ char smr[];
    uint32_t* QH = (uint32_t*)smr;                   // [128][68] tf32-hi   [0, 34816)
    uint32_t* QL = (uint32_t*)(smr + 34816);         // [128][68] tf32-lo   [34816, 69632)
    uint32_t* KH = (uint32_t*)(smr + 69632);         // [128][68] tf32-hi   [69632, 104448)
    float*    mC = (float*)(smr + 104448);           // [128] mask*(-1e9)-16
    uint32_t* VH = (uint32_t*)smr;                   // [128][72] hi (Pass B, over QH/QL)
    float* rowSp = (float*)(smr + 73728);            // [2][128] (inside dead KH)

    const int tid  = threadIdx.x;
    const int lane = tid & 31;
    const int warp = tid >> 5;
    const int wm   = warp & 3;
    const int wn   = warp >> 2;
    const int ra   = lane >> 2;
    const int qc   = lane & 3;
    const int rb   = wm * 32;
    const int bh   = blockIdx.y;
    const int b    = bh >> 4;
    const int q0   = blockIdx.x << 7;

    const float* Qb = g_Qh + ((size_t)bh << 16);
    const float* Kb = g_Kh + ((size_t)bh << 16);
    const float* Vb = g_Vh + ((size_t)bh << 16);
    float* Ab = attn + ((size_t)bh << 20);

#pragma unroll
    for (int i = 0; i < 8; i++) {
        int f4 = tid + (i << 8);
        int r = f4 >> 4, cc = (f4 & 15) << 2;
        float4 v = *reinterpret_cast<const float4*>(&Qb[(size_t)(q0 + r) * 64 + cc]);
        uint4 h, l;
        tfsplit(v.x, h.x, l.x); tfsplit(v.y, h.y, l.y);
        tfsplit(v.z, h.z, l.z); tfsplit(v.w, h.w, l.w);
        *reinterpret_cast<uint4*>(&QH[r * 68 + cc]) = h;
        *reinterpret_cast<uint4*>(&QL[r * 68 + cc]) = l;
    }

    float sAcc[2][2] = {{0.f, 0.f}, {0.f, 0.f}};

    // ---- Pass A ----
    for (int kt = 0; kt < 8; kt++) {
        __syncthreads();
#pragma unroll
        for (int i = 0; i < 8; i++) {
            int f4 = tid + (i << 8);
            int r = f4 >> 4, cc = (f4 & 15) << 2;
            float4 v = *reinterpret_cast<const float4*>(&Kb[(size_t)(kt * 128 + r) * 64 + cc]);
            uint4 h;
            h.x = f2tf(v.x); h.y = f2tf(v.y); h.z = f2tf(v.z); h.w = f2tf(v.w);
            *reinterpret_cast<uint4*>(&KH[r * 68 + cc]) = h;
        }
        if (tid < 128) mC[tid] = mask[b * 1024 + kt * 128 + tid] * (-1e9f) - 16.0f;
        __syncthreads();

        float s[2][8][4];
#pragma unroll
        for (int mt = 0; mt < 2; mt++)
#pragma unroll
            for (int nt = 0; nt < 8; nt++) {
                s[mt][nt][0] = 0.f; s[mt][nt][1] = 0.f; s[mt][nt][2] = 0.f; s[mt][nt][3] = 0.f;
            }

#pragma unroll
        for (int ks = 0; ks < 8; ks++) {
            int kk = ks << 3;
            uint32_t ah[2][4], al[2][4];
#pragma unroll
            for (int mt = 0; mt < 2; mt++) {
                int row = rb + mt * 16 + ra;
                ah[mt][0] = QH[row * 68 + kk + qc];
                ah[mt][1] = QH[(row + 8) * 68 + kk + qc];
                ah[mt][2] = QH[row * 68 + kk + qc + 4];
                ah[mt][3] = QH[(row + 8) * 68 + kk + qc + 4];
                al[mt][0] = QL[row * 68 + kk + qc];
                al[mt][1] = QL[(row + 8) * 68 + kk + qc];
                al[mt][2] = QL[row * 68 + kk + qc + 4];
                al[mt][3] = QL[(row + 8) * 68 + kk + qc + 4];
            }
#pragma unroll
            for (int nt = 0; nt < 8; nt++) {
                int key = wn * 64 + nt * 8 + ra;
                uint32_t bh2[2] = { KH[key * 68 + kk + qc], KH[key * 68 + kk + qc + 4] };
                mma8(s[0][nt], ah[0], bh2);
                mma8(s[0][nt], al[0], bh2);
                mma8(s[1][nt], ah[1], bh2);
                mma8(s[1][nt], al[1], bh2);
            }
        }

#pragma unroll
        for (int mt = 0; mt < 2; mt++) {
#pragma unroll
            for (int nt = 0; nt < 8; nt++) {
                int c0 = wn * 64 + nt * 8 + (qc << 1);
                float m0 = mC[c0], m1 = mC[c0 + 1];
                float p0 = __expf(fmaf(s[mt][nt][0], 0.125f, m0));
                float p1 = __expf(fmaf(s[mt][nt][1], 0.125f, m1));
                float p2 = __expf(fmaf(s[mt][nt][2], 0.125f, m0));
                float p3 = __expf(fmaf(s[mt][nt][3], 0.125f, m1));
                sAcc[mt][0] += p0 + p1;
                sAcc[mt][1] += p2 + p3;
                float* p = Ab + (size_t)(q0 + rb + mt * 16 + ra) * 1024 + kt * 128 + c0;
                *reinterpret_cast<float2*>(p) = make_float2(p0, p1);
                *reinterpret_cast<float2*>(p + 8192) = make_float2(p2, p3);
            }
        }
    }

    // ---- rowsum ----
#pragma unroll
    for (int mt = 0; mt < 2; mt++)
#pragma unroll
        for (int j = 0; j < 2; j++) {
            sAcc[mt][j] += __shfl_xor_sync(0xffffffffu, sAcc[mt][j], 1);
            sAcc[mt][j] += __shfl_xor_sync(0xffffffffu, sAcc[mt][j], 2);
        }
    __syncthreads();
    if (qc == 0) {
#pragma unroll
        for (int mt = 0; mt < 2; mt++) {
            rowSp[wn * 128 + rb + mt * 16 + ra]     = sAcc[mt][0];
            rowSp[wn * 128 + rb + mt * 16 + ra + 8] = sAcc[mt][1];
        }
    }
    __syncthreads();

    // ---- Pass B ----
    const int r0 = warp << 4;
    const float iAr = 1.0f / (rowSp[r0 + ra]     + rowSp[128 + r0 + ra]);
    const float iBr = 1.0f / (rowSp[r0 + ra + 8] + rowSp[128 + r0 + ra + 8]);

    float cf[8][4];
#pragma unroll
    for (int nt = 0; nt < 8; nt++) { cf[nt][0] = 0.f; cf[nt][1] = 0.f; cf[nt][2] = 0.f; cf[nt][3] = 0.f; }

    for (int kt = 0; kt < 8; kt++) {
        __syncthreads();
#pragma unroll
        for (int i = 0; i < 8; i++) {
            int f4 = tid + (i << 8);
            int r = f4 >> 4, cc = (f4 & 15) << 2;
            float4 v = *reinterpret_cast<const float4*>(&Vb[(size_t)(kt * 128 + r) * 64 + cc]);
            uint4 h;
            h.x = f2tf(v.x); h.y = f2tf(v.y); h.z = f2tf(v.z); h.w = f2tf(v.w);
            *reinterpret_cast<uint4*>(&VH[r * 72 + cc]) = h;
        }
        __syncthreads();

#pragma unroll
        for (int k2 = 0; k2 < 16; k2++) {
            float* pA = Ab + (size_t)(q0 + r0 + ra) * 1024 + kt * 128 + k2 * 8 + qc;
            float* pB = pA + 8192;
            float a0 = pA[0] * iAr, a2 = pA[4] * iAr;
            float a1 = pB[0] * iBr, a3 = pB[4] * iBr;
            pA[0] = a0; pA[4] = a2; pB[0] = a1; pB[4] = a3;

            uint32_t ah[4], al[4];
            tfsplit(a0, ah[0], al[0]);
            tfsplit(a1, ah[1], al[1]);
            tfsplit(a2, ah[2], al[2]);
            tfsplit(a3, ah[3], al[3]);

            int kl = k2 * 8 + qc;
#pragma unroll
            for (int nt = 0; nt < 8; nt++) {
                int dim = nt * 8 + ra;
                uint32_t bh2[2] = { VH[kl * 72 + dim], VH[(kl + 4) * 72 + dim] };
                mma8(cf[nt], ah, bh2);
                mma8(cf[nt], al, bh2);
            }
        }
    }

    // ctx epilogue: (B, S, H*64)
    const int h = bh & 15;
#pragma unroll
    for (int nt = 0; nt < 8; nt++) {
        int dim = nt * 8 + (qc << 1);
        size_t base = (size_t)(b * 1024 + q0 + r0 + ra) * 1024 + h * 64 + dim;
        *reinterpret_cast<float2*>(&g_ctx[base]) = make_float2(cf[nt][0], cf[nt][1]);
        *reinterpret_cast<float2*>(&g_ctx[base + 8192]) = make_float2(cf[nt][2], cf[nt][3]);
    }
}

// ---------------- launch ----------------
extern "C" void kernel_launch(void* const* d_in, const int* in_sizes, int n_in,
                              void* d_out, int out_size) {
    (void)in_sizes; (void)n_in;
    const float* q    = (const float*)d_in[0];
    const float* k    = (const float*)d_in[1];
    const float* v    = (const float*)d_in[2];
    const float* mask = (const float*)d_in[3];
    const float* wq   = (const float*)d_in[4];
    const float* bq   = (const float*)d_in[5];
    const float* wk   = (const float*)d_in[6];
    const float* bk   = (const float*)d_in[7];
    const float* wv   = (const float*)d_in[8];
    const float* bv   = (const float*)d_in[9];
    const float* wo   = (const float*)d_in[10];
    const float* bo   = (const float*)d_in[11];
    float* outp = (float*)d_out;

    float *pQ, *pK, *pV, *pC;
    cudaGetSymbolAddress((void**)&pQ, g_Qh);
    cudaGetSymbolAddress((void**)&pK, g_Kh);
    cudaGetSymbolAddress((void**)&pV, g_Vh);
    cudaGetSymbolAddress((void**)&pC, g_ctx);

    float* attnp;
    if (out_size > OUT_ELEMS) {
        attnp = outp + OUT_ELEMS;           // (out, attn) concatenated in d_out
    } else {
        cudaGetSymbolAddress((void**)&attnp, g_attn);
    }

    const int GEMM_SMEM = 33792;            // AH+AL+WH+WL
    const int ATTN_SMEM = 104960;
    cudaFuncSetAttribute(gemm_bf16, cudaFuncAttributeMaxDynamicSharedMemorySize, GEMM_SMEM);
    cudaFuncSetAttribute(attn_kernel, cudaFuncAttributeMaxDynamicSharedMemorySize, ATTN_SMEM);

    dim3 gg(8, 64);   // N/128 x M/128
    gemm_bf16<<<gg, 256, GEMM_SMEM>>>(q, wq, bq, pQ, 1);
    gemm_bf16<<<gg, 256, GEMM_SMEM>>>(k, wk, bk, pK, 1);
    gemm_bf16<<<gg, 256, GEMM_SMEM>>>(v, wv, bv, pV, 1);
    attn_kernel<<<dim3(8, 128), 256, ATTN_SMEM>>>(mask, attnp);
    gemm_bf16<<<gg, 256, GEMM_SMEM>>>(pC, wo, bo, outp, 0);
}